// round 5
// baseline (speedup 1.0000x reference)
#include <cuda_runtime.h>
#include <cuda_bf16.h>
#include <math.h>

// Problem constants
#define B_   4
#define L_   4096
#define D_   1024
#define H_   16
#define M_   (B_ * L_)          // 16384
#define K2   2048               // stored split: [hi | lo]; logical K3=3072 aliased
#define KLOG 3072
#define EPS_ 1e-5f

// GEMM tile config (mma.sync path): 128x256 CTA tile, 8 warps of 64x64
#define BM 128
#define BN 256
#define BK 64                       // bf16 per chunk (128 B rows, SW128)
#define NCHUNK (KLOG / BK)          // 48
#define A_TILE_BYTES (BM * 128)     // 16 KB
#define B_TILE_BYTES (BN * 128)     // 32 KB
#define STAGE_BYTES (A_TILE_BYTES + B_TILE_BYTES)   // 48 KB
#define NSTAGE 3
#define DSMEM_BYTES (NSTAGE * STAGE_BYTES + 1024)   // 145 KB

// ---------------------------------------------------------------------------
// Scratch (device globals)
// ---------------------------------------------------------------------------
__device__ __align__(128) __nv_bfloat16 g_Qs [(size_t)M_ * K2];
__device__ __align__(128) __nv_bfloat16 g_VNs[(size_t)M_ * K2];
__device__ __align__(128) __nv_bfloat16 g_Wq [(size_t)D_ * K2];
__device__ __align__(128) __nv_bfloat16 g_Wk [(size_t)D_ * K2];
__device__ __align__(128) __nv_bfloat16 g_Wv [(size_t)D_ * K2];
__device__ __align__(128) __nv_bfloat16 g_Wo [(size_t)D_ * K2];
__device__ __align__(128) float g_phiq[(size_t)M_ * D_];
__device__ __align__(128) float g_phik[(size_t)M_ * D_];
__device__ __align__(128) float g_v   [(size_t)M_ * D_];
__device__ __align__(128) float g_KV  [64 * 64 * 64];
__device__ __align__(128) float g_Ksum[64 * 64];

// ---------------------------------------------------------------------------
// Helpers
// ---------------------------------------------------------------------------
__device__ __forceinline__ unsigned smem_u32(const void* p) {
    unsigned a;
    asm("{ .reg .u64 t; cvta.to.shared.u64 t, %1; cvt.u32.u64 %0, t; }"
        : "=r"(a) : "l"(p));
    return a;
}
#define SWZ(o) ((o) ^ ((((unsigned)(o)) >> 3) & 0x70))

#define CP_ASYNC16(dst, src) \
    asm volatile("cp.async.cg.shared.global [%0], [%1], 16;" :: "r"(dst), "l"(src))
#define CP_COMMIT() asm volatile("cp.async.commit_group;" ::: "memory")
#define CP_WAIT1()  asm volatile("cp.async.wait_group 1;" ::: "memory")
#define CP_WAIT0()  asm volatile("cp.async.wait_group 0;" ::: "memory")

#define LDSM4(r, a) \
    asm volatile("ldmatrix.sync.aligned.m8n8.x4.shared.b16 {%0,%1,%2,%3}, [%4];" \
                 : "=r"((r)[0]), "=r"((r)[1]), "=r"((r)[2]), "=r"((r)[3]) : "r"(a))

#define MMA16816(c, a, b) \
    asm volatile("mma.sync.aligned.m16n8k16.row.col.f32.bf16.bf16.f32 " \
                 "{%0,%1,%2,%3}, {%4,%5,%6,%7}, {%8,%9}, {%0,%1,%2,%3};" \
                 : "+f"((c)[0]), "+f"((c)[1]), "+f"((c)[2]), "+f"((c)[3]) \
                 : "r"((a)[0]), "r"((a)[1]), "r"((a)[2]), "r"((a)[3]),   \
                   "r"((b)[0]), "r"((b)[1]))

// ---------------------------------------------------------------------------
// Chunk loader: gmem (bf16, K2-stride rows) -> swizzled SMEM (cp.async)
// Logical chunk (of K3=3072): A [hi|lo|hi] -> kA = kb>=2048 ? kb-2048 : kb
//                             B [hi|hi|lo] -> kB = kb<1024 ? kb : kb-1024
// ---------------------------------------------------------------------------
__device__ __forceinline__ void load_chunk(
    const __nv_bfloat16* __restrict__ A, const __nv_bfloat16* __restrict__ W,
    unsigned sbase, int stage, int chunk, int row0, int col0, int t)
{
    const int kb = chunk * BK;
    const int kA = (kb >= 2048) ? kb - 2048 : kb;
    const int kB = (kb < 1024) ? kb : kb - 1024;
    unsigned As = sbase + stage * STAGE_BYTES;
    unsigned Bs = As + A_TILE_BYTES;
    const int r = t >> 3, cc = t & 7;
#pragma unroll
    for (int i = 0; i < 4; i++) {
        const void* src = A + (size_t)(row0 + r + i * 32) * K2 + kA + cc * 8;
        CP_ASYNC16(As + SWZ((r + i * 32) * 128 + cc * 16), src);
    }
#pragma unroll
    for (int i = 0; i < 8; i++) {
        const void* src = W + (size_t)(col0 + r + i * 32) * K2 + kB + cc * 8;
        CP_ASYNC16(Bs + SWZ((r + i * 32) * 128 + cc * 16), src);
    }
}

// ---------------------------------------------------------------------------
// mma.sync GEMM: C[m,n] = sum_k3 A'[m,k] B'[n,k] + bias[n], optional phi
// 256 threads = 8 warps (2 m x 4 n); warp computes 64x64. 3-stage pipeline.
// ---------------------------------------------------------------------------
__device__ __forceinline__ void tc_gemm_body(
    const __nv_bfloat16* __restrict__ A, const __nv_bfloat16* __restrict__ W,
    const float* __restrict__ bias, float* __restrict__ C, int act)
{
    extern __shared__ char dsm_raw[];
    unsigned draw = smem_u32(dsm_raw);
    unsigned sbase = (draw + 1023u) & ~1023u;

    const int t = threadIdx.x;
    const int wid = t >> 5, lane = t & 31;
    const int warp_m = wid & 1, warp_n = wid >> 1;
    const int row0 = blockIdx.y * BM;
    const int col0 = blockIdx.x * BN;

    float acc[4][8][4];
#pragma unroll
    for (int i = 0; i < 4; i++)
#pragma unroll
        for (int j = 0; j < 8; j++)
#pragma unroll
            for (int q = 0; q < 4; q++) acc[i][j][q] = 0.f;

    load_chunk(A, W, sbase, 0, 0, row0, col0, t);
    CP_COMMIT();
    load_chunk(A, W, sbase, 1, 1, row0, col0, t);
    CP_COMMIT();

    const int a_row = lane & 15, a_kb = (lane >> 4) * 16;
    const int b_g = lane >> 3;
    const int b_row = ((b_g >> 1) * 8) + (lane & 7);
    const int b_kb = (b_g & 1) * 16;

    int stage = 0;
    for (int c = 0; c < NCHUNK; c++) {
        if (c == NCHUNK - 1) { CP_WAIT0(); } else { CP_WAIT1(); }
        __syncthreads();
        if (c + 2 < NCHUNK) {
            int ns = stage + 2; if (ns >= NSTAGE) ns -= NSTAGE;
            load_chunk(A, W, sbase, ns, c + 2, row0, col0, t);
            CP_COMMIT();
        }

        unsigned As = sbase + stage * STAGE_BYTES;
        unsigned Bs = As + A_TILE_BYTES;
#pragma unroll
        for (int ks = 0; ks < 4; ks++) {
            unsigned a[4][4], b[8][2];
#pragma unroll
            for (int mt = 0; mt < 4; mt++) {
                int row = warp_m * 64 + mt * 16 + a_row;
                LDSM4(a[mt], As + SWZ(row * 128 + ks * 32 + a_kb));
            }
#pragma unroll
            for (int np = 0; np < 4; np++) {
                int row = warp_n * 64 + np * 16 + b_row;
                unsigned r4[4];
                LDSM4(r4, Bs + SWZ(row * 128 + ks * 32 + b_kb));
                b[np * 2][0] = r4[0]; b[np * 2][1] = r4[1];
                b[np * 2 + 1][0] = r4[2]; b[np * 2 + 1][1] = r4[3];
            }
#pragma unroll
            for (int mt = 0; mt < 4; mt++)
#pragma unroll
                for (int nt = 0; nt < 8; nt++)
                    MMA16816(acc[mt][nt], a[mt], b[nt]);
        }
        stage++; if (stage >= NSTAGE) stage = 0;
    }

    // Epilogue
#pragma unroll
    for (int mt = 0; mt < 4; mt++) {
        int row = row0 + warp_m * 64 + mt * 16 + (lane >> 2);
#pragma unroll
        for (int nt = 0; nt < 8; nt++) {
            int col = col0 + warp_n * 64 + nt * 8 + (lane & 3) * 2;
            float bv0 = bias[col], bv1 = bias[col + 1];
            float o0 = acc[mt][nt][0] + bv0;
            float o1 = acc[mt][nt][1] + bv1;
            float o2 = acc[mt][nt][2] + bv0;
            float o3 = acc[mt][nt][3] + bv1;
            if (act) {
                o0 = o0 > 0.f ? o0 + 1.f : __expf(o0);
                o1 = o1 > 0.f ? o1 + 1.f : __expf(o1);
                o2 = o2 > 0.f ? o2 + 1.f : __expf(o2);
                o3 = o3 > 0.f ? o3 + 1.f : __expf(o3);
            }
            *(float2*)(C + (size_t)row * D_ + col)       = make_float2(o0, o1);
            *(float2*)(C + (size_t)(row + 8) * D_ + col) = make_float2(o2, o3);
        }
    }
}

__global__ __launch_bounds__(256, 1) void qkv_tc(
    const float* __restrict__ bQ, const float* __restrict__ bK,
    const float* __restrict__ bV)
{
    const int z = blockIdx.z;
    const __nv_bfloat16* W = (z == 0) ? g_Wq : (z == 1) ? g_Wk : g_Wv;
    const float* bb        = (z == 0) ? bQ   : (z == 1) ? bK   : bV;
    float* C               = (z == 0) ? g_phiq : (z == 1) ? g_phik : g_v;
    tc_gemm_body(g_Qs, W, bb, C, z < 2);
}

__global__ __launch_bounds__(256, 1) void out_tc(
    const float* __restrict__ bO, float* __restrict__ out)
{
    tc_gemm_body(g_VNs, g_Wo, bO, out, 0);
}

// ---------------------------------------------------------------------------
// fp32 -> bf16 2-term split, stored [hi | lo] with K2 row stride
// ---------------------------------------------------------------------------
__device__ __forceinline__ void split_one(
    const float* __restrict__ in, __nv_bfloat16* __restrict__ out, size_t i)
{
    const float2 x = ((const float2*)in)[i];
    size_t r = i >> 9;
    int c2 = (int)(i & 511);
    __nv_bfloat16 h0 = __float2bfloat16(x.x), h1 = __float2bfloat16(x.y);
    __nv_bfloat16 l0 = __float2bfloat16(x.x - __bfloat162float(h0));
    __nv_bfloat16 l1 = __float2bfloat16(x.y - __bfloat162float(h1));
    unsigned hv = ((unsigned)__bfloat16_as_ushort(h1) << 16) | __bfloat16_as_ushort(h0);
    unsigned lv = ((unsigned)__bfloat16_as_ushort(l1) << 16) | __bfloat16_as_ushort(l0);
    unsigned* o = (unsigned*)(out + r * K2) + c2;
    o[0] = hv; o[512] = lv;
}

__global__ __launch_bounds__(256) void split_q_kernel(const float* __restrict__ Q)
{
    split_one(Q, g_Qs, (size_t)blockIdx.x * 256 + threadIdx.x);
}

__global__ __launch_bounds__(256) void split_w_kernel(
    const float* __restrict__ WQ, const float* __restrict__ WK,
    const float* __restrict__ WV, const float* __restrict__ WO)
{
    const int z = blockIdx.y;
    const float* in = (z == 0) ? WQ : (z == 1) ? WK : (z == 2) ? WV : WO;
    __nv_bfloat16* out = (z == 0) ? g_Wq : (z == 1) ? g_Wk : (z == 2) ? g_Wv : g_Wo;
    split_one(in, out, (size_t)blockIdx.x * 256 + threadIdx.x);
}

// ---------------------------------------------------------------------------
// Zero accumulators
// ---------------------------------------------------------------------------
__global__ void zero_acc_kernel()
{
    int i = blockIdx.x * 256 + threadIdx.x;
    if (i < 64 * 64 * 64) g_KV[i] = 0.f;
    if (i < 64 * 64)      g_Ksum[i] = 0.f;
}

// ---------------------------------------------------------------------------
// KV[bh][d][m] accumulation + K_sum
// ---------------------------------------------------------------------------
__global__ __launch_bounds__(256) void kv_kernel()
{
    const int bh = blockIdx.x;
    const int b = bh >> 4, h = bh & 15;
    const int l0 = blockIdx.y * 512;

    __shared__ float ks[16][64];
    __shared__ float vs[16][64];

    const int t = threadIdx.x;
    const int td = t >> 4, tmm = t & 15;
    const int lr = t >> 4, lc = (t & 15) * 4;

    float acc[4][4];
    float ksum[4] = {0.f, 0.f, 0.f, 0.f};
#pragma unroll
    for (int i = 0; i < 4; i++)
#pragma unroll
        for (int j = 0; j < 4; j++) acc[i][j] = 0.f;

    for (int lt = 0; lt < 512; lt += 16) {
        size_t base = ((size_t)(b * L_ + l0 + lt + lr)) * D_ + h * 64 + lc;
        float4 kq = *(const float4*)(g_phik + base);
        float4 vq = *(const float4*)(g_v + base);
        __syncthreads();
        *(float4*)&ks[lr][lc] = kq;
        *(float4*)&vs[lr][lc] = vq;
        __syncthreads();
#pragma unroll
        for (int ll = 0; ll < 16; ll++) {
            float ka[4], va[4];
#pragma unroll
            for (int i = 0; i < 4; i++) ka[i] = ks[ll][td * 4 + i];
#pragma unroll
            for (int j = 0; j < 4; j++) va[j] = vs[ll][tmm * 4 + j];
#pragma unroll
            for (int i = 0; i < 4; i++)
#pragma unroll
                for (int j = 0; j < 4; j++) acc[i][j] += ka[i] * va[j];
            if (tmm == 0) {
#pragma unroll
                for (int i = 0; i < 4; i++) ksum[i] += ka[i];
            }
        }
    }

    float* kvout = g_KV + bh * 4096;
#pragma unroll
    for (int i = 0; i < 4; i++)
#pragma unroll
        for (int j = 0; j < 4; j++)
            atomicAdd(&kvout[(td * 4 + i) * 64 + tmm * 4 + j], acc[i][j]);
    if (tmm == 0) {
#pragma unroll
        for (int i = 0; i < 4; i++)
            atomicAdd(&g_Ksum[bh * 64 + td * 4 + i], ksum[i]);
    }
}

// ---------------------------------------------------------------------------
// V_new: warp handles 4 rows per pass; d-loop vectorized (float4 pq reads).
// Writes bf16 split [hi|lo] into g_VNs (K2 stride).
// ---------------------------------------------------------------------------
__global__ __launch_bounds__(256) void vnew_kernel()
{
    const int bh = blockIdx.x;
    const int b = bh >> 4, h = bh & 15;
    const int l0 = blockIdx.y * 512;

    __shared__ float KVs[64][64];
    __shared__ float Ks[64];
    __shared__ float pqs[8][4][64];

    const int t = threadIdx.x, w = t >> 5, lane = t & 31;

    for (int i = t; i < 1024; i += 256)
        ((float4*)KVs)[i] = ((const float4*)(g_KV + bh * 4096))[i];
    if (t < 64) Ks[t] = g_Ksum[bh * 64 + t];
    __syncthreads();

    const int prow = lane >> 3;          // 0..3
    const int pcol = (lane & 7) * 8;     // 0..56

    for (int s = 0; s < 16; s++) {
        const int lb = l0 + s * 32 + w * 4;
        const float* pq = g_phiq + ((size_t)(b * L_ + lb + prow)) * D_ + h * 64 + pcol;
        float4 pa = *(const float4*)pq;
        float4 pb = *(const float4*)(pq + 4);
        *(float4*)&pqs[w][prow][pcol]     = pa;
        *(float4*)&pqs[w][prow][pcol + 4] = pb;

        float zp = pa.x * Ks[pcol]     + pa.y * Ks[pcol + 1]
                 + pa.z * Ks[pcol + 2] + pa.w * Ks[pcol + 3]
                 + pb.x * Ks[pcol + 4] + pb.y * Ks[pcol + 5]
                 + pb.z * Ks[pcol + 6] + pb.w * Ks[pcol + 7];
        zp += __shfl_xor_sync(0xffffffffu, zp, 1);
        zp += __shfl_xor_sync(0xffffffffu, zp, 2);
        zp += __shfl_xor_sync(0xffffffffu, zp, 4);
        float z0 = 1.f / (__shfl_sync(0xffffffffu, zp, 0)  + EPS_);
        float z1 = 1.f / (__shfl_sync(0xffffffffu, zp, 8)  + EPS_);
        float z2 = 1.f / (__shfl_sync(0xffffffffu, zp, 16) + EPS_);
        float z3 = 1.f / (__shfl_sync(0xffffffffu, zp, 24) + EPS_);
        __syncwarp();

        float2 a0 = {0.f, 0.f}, a1 = {0.f, 0.f}, a2 = {0.f, 0.f}, a3 = {0.f, 0.f};
        const float4* q40 = (const float4*)&pqs[w][0][0];
        const float4* q41 = (const float4*)&pqs[w][1][0];
        const float4* q42 = (const float4*)&pqs[w][2][0];
        const float4* q43 = (const float4*)&pqs[w][3][0];
#pragma unroll
        for (int d4 = 0; d4 < 16; d4++) {
            float4 q0 = q40[d4], q1 = q41[d4], q2 = q42[d4], q3 = q43[d4];
            float2 kv0 = *(const float2*)&KVs[d4 * 4 + 0][lane * 2];
            float2 kv1 = *(const float2*)&KVs[d4 * 4 + 1][lane * 2];
            float2 kv2 = *(const float2*)&KVs[d4 * 4 + 2][lane * 2];
            float2 kv3 = *(const float2*)&KVs[d4 * 4 + 3][lane * 2];
            a0.x += q0.x * kv0.x + q0.y * kv1.x + q0.z * kv2.x + q0.w * kv3.x;
            a0.y += q0.x * kv0.y + q0.y * kv1.y + q0.z * kv2.y + q0.w * kv3.y;
            a1.x += q1.x * kv0.x + q1.y * kv1.x + q1.z * kv2.x + q1.w * kv3.x;
            a1.y += q1.x * kv0.y + q1.y * kv1.y + q1.z * kv2.y + q1.w * kv3.y;
            a2.x += q2.x * kv0.x + q2.y * kv1.x + q2.z * kv2.x + q2.w * kv3.x;
            a2.y += q2.x * kv0.y + q2.y * kv1.y + q2.z * kv2.y + q2.w * kv3.y;
            a3.x += q3.x * kv0.x + q3.y * kv1.x + q3.z * kv2.x + q3.w * kv3.x;
            a3.y += q3.x * kv0.y + q3.y * kv1.y + q3.z * kv2.y + q3.w * kv3.y;
        }

        float2 vv[4] = {
            {a0.x * z0, a0.y * z0}, {a1.x * z1, a1.y * z1},
            {a2.x * z2, a2.y * z2}, {a3.x * z3, a3.y * z3}
        };
#pragma unroll
        for (int j = 0; j < 4; j++) {
            __nv_bfloat16 h0 = __float2bfloat16(vv[j].x);
            __nv_bfloat16 h1 = __float2bfloat16(vv[j].y);
            __nv_bfloat16 q0 = __float2bfloat16(vv[j].x - __bfloat162float(h0));
            __nv_bfloat16 q1 = __float2bfloat16(vv[j].y - __bfloat162float(h1));
            unsigned hv = ((unsigned)__bfloat16_as_ushort(h1) << 16) | __bfloat16_as_ushort(h0);
            unsigned lv = ((unsigned)__bfloat16_as_ushort(q1) << 16) | __bfloat16_as_ushort(q0);
            unsigned* p = (unsigned*)(g_VNs + (size_t)(b * L_ + lb + j) * K2) + h * 32 + lane;
            p[0] = hv; p[512] = lv;
        }
        __syncwarp();
    }
}

// ---------------------------------------------------------------------------
// Launch
// ---------------------------------------------------------------------------
extern "C" void kernel_launch(void* const* d_in, const int* in_sizes, int n_in,
                              void* d_out, int out_size)
{
    const float* Q  = (const float*)d_in[0];
    const float* WQ = (const float*)d_in[1];
    const float* bQ = (const float*)d_in[2];
    const float* WK = (const float*)d_in[3];
    const float* bK = (const float*)d_in[4];
    const float* WV = (const float*)d_in[5];
    const float* bV = (const float*)d_in[6];
    const float* WO = (const float*)d_in[7];
    const float* bO = (const float*)d_in[8];
    float* out = (float*)d_out;

    cudaFuncSetAttribute(qkv_tc, cudaFuncAttributeMaxDynamicSharedMemorySize, DSMEM_BYTES);
    cudaFuncSetAttribute(out_tc, cudaFuncAttributeMaxDynamicSharedMemorySize, DSMEM_BYTES);

    zero_acc_kernel<<<1024, 256>>>();

    split_q_kernel<<<(M_ * 512) / 256, 256>>>(Q);
    {
        dim3 grid((D_ * 512) / 256, 4);
        split_w_kernel<<<grid, 256>>>(WQ, WK, WV, WO);
    }

    {
        dim3 grid(D_ / BN, M_ / BM, 3);
        qkv_tc<<<grid, 256, DSMEM_BYTES>>>(bQ, bK, bV);
    }
    {
        dim3 grid(64, 8);
        kv_kernel<<<grid, 256>>>();
    }
    {
        dim3 grid(64, 8);
        vnew_kernel<<<grid, 256>>>();
    }
    {
        dim3 grid(D_ / BN, M_ / BM);
        out_tc<<<grid, 256, DSMEM_BYTES>>>(bO, out);
    }
}

// round 6
// speedup vs baseline: 1.0819x; 1.0819x over previous
#include <cuda_runtime.h>
#include <cuda_bf16.h>
#include <math.h>

// Problem constants
#define B_   4
#define L_   4096
#define D_   1024
#define H_   16
#define M_   (B_ * L_)          // 16384
#define K2   2048               // stored split: [hi | lo]; logical K3=3072 aliased
#define KLOG 3072
#define EPS_ 1e-5f

// GEMM tile config (mma.sync path): 128x128 CTA tile, 8 warps of 32x64
#define BM 128
#define BN 128
#define BK 64                       // bf16 per chunk (128 B rows, SW128)
#define NCHUNK (KLOG / BK)          // 48
#define TILE_BYTES (BM * 128)       // 16 KB
#define STAGE_BYTES (2 * TILE_BYTES)
#define NSTAGE 3
#define DSMEM_BYTES (NSTAGE * STAGE_BYTES + 1024)

// ---------------------------------------------------------------------------
// Scratch (device globals)
// ---------------------------------------------------------------------------
__device__ __align__(128) __nv_bfloat16 g_Qs [(size_t)M_ * K2];
__device__ __align__(128) __nv_bfloat16 g_VNs[(size_t)M_ * K2];
__device__ __align__(128) __nv_bfloat16 g_Wq [(size_t)D_ * K2];
__device__ __align__(128) __nv_bfloat16 g_Wk [(size_t)D_ * K2];
__device__ __align__(128) __nv_bfloat16 g_Wv [(size_t)D_ * K2];
__device__ __align__(128) __nv_bfloat16 g_Wo [(size_t)D_ * K2];
__device__ __align__(128) float g_phiq[(size_t)M_ * D_];
__device__ __align__(128) float g_phik[(size_t)M_ * D_];
__device__ __align__(128) float g_v   [(size_t)M_ * D_];
__device__ __align__(128) float g_KV  [64 * 64 * 64];
__device__ __align__(128) float g_Ksum[64 * 64];

// ---------------------------------------------------------------------------
// Helpers
// ---------------------------------------------------------------------------
__device__ __forceinline__ unsigned smem_u32(const void* p) {
    unsigned a;
    asm("{ .reg .u64 t; cvta.to.shared.u64 t, %1; cvt.u32.u64 %0, t; }"
        : "=r"(a) : "l"(p));
    return a;
}
#define SWZ(o) ((o) ^ ((((unsigned)(o)) >> 3) & 0x70))

#define CP_ASYNC16(dst, src) \
    asm volatile("cp.async.cg.shared.global [%0], [%1], 16;" :: "r"(dst), "l"(src))
#define CP_COMMIT() asm volatile("cp.async.commit_group;" ::: "memory")
#define CP_WAIT1()  asm volatile("cp.async.wait_group 1;" ::: "memory")
#define CP_WAIT0()  asm volatile("cp.async.wait_group 0;" ::: "memory")

#define LDSM4(r, a) \
    asm volatile("ldmatrix.sync.aligned.m8n8.x4.shared.b16 {%0,%1,%2,%3}, [%4];" \
                 : "=r"((r)[0]), "=r"((r)[1]), "=r"((r)[2]), "=r"((r)[3]) : "r"(a))

#define MMA16816(c, a, b) \
    asm volatile("mma.sync.aligned.m16n8k16.row.col.f32.bf16.bf16.f32 " \
                 "{%0,%1,%2,%3}, {%4,%5,%6,%7}, {%8,%9}, {%0,%1,%2,%3};" \
                 : "+f"((c)[0]), "+f"((c)[1]), "+f"((c)[2]), "+f"((c)[3]) \
                 : "r"((a)[0]), "r"((a)[1]), "r"((a)[2]), "r"((a)[3]),   \
                   "r"((b)[0]), "r"((b)[1]))

// ---------------------------------------------------------------------------
// Chunk loader: gmem (bf16, K2-stride rows) -> swizzled SMEM (cp.async)
// Logical chunk (of K3=3072): A [hi|lo|hi] -> kA = kb>=2048 ? kb-2048 : kb
//                             B [hi|hi|lo] -> kB = kb<1024 ? kb : kb-1024
// ---------------------------------------------------------------------------
__device__ __forceinline__ void load_chunk(
    const __nv_bfloat16* __restrict__ A, const __nv_bfloat16* __restrict__ W,
    unsigned sbase, int stage, int chunk, int row0, int col0, int t)
{
    const int kb = chunk * BK;
    const int kA = (kb >= 2048) ? kb - 2048 : kb;
    const int kB = (kb < 1024) ? kb : kb - 1024;
    unsigned As = sbase + stage * STAGE_BYTES;
    unsigned Bs = As + TILE_BYTES;
    const int r = t >> 3, cc = t & 7;
#pragma unroll
    for (int i = 0; i < 4; i++) {
        const void* src = A + (size_t)(row0 + r + i * 32) * K2 + kA + cc * 8;
        CP_ASYNC16(As + SWZ((r + i * 32) * 128 + cc * 16), src);
    }
#pragma unroll
    for (int i = 0; i < 4; i++) {
        const void* src = W + (size_t)(col0 + r + i * 32) * K2 + kB + cc * 8;
        CP_ASYNC16(Bs + SWZ((r + i * 32) * 128 + cc * 16), src);
    }
}

// ---------------------------------------------------------------------------
// mma.sync GEMM: C[m,n] = sum_k3 A'[m,k] B'[n,k] + bias[n], optional phi
// 256 threads = 8 warps (4 m x 2 n); warp computes 32x64. 3-stage pipeline.
// ---------------------------------------------------------------------------
__device__ __forceinline__ void tc_gemm_body(
    const __nv_bfloat16* __restrict__ A, const __nv_bfloat16* __restrict__ W,
    const float* __restrict__ bias, float* __restrict__ C, int act)
{
    extern __shared__ char dsm_raw[];
    unsigned draw = smem_u32(dsm_raw);
    unsigned sbase = (draw + 1023u) & ~1023u;

    const int t = threadIdx.x;
    const int wid = t >> 5, lane = t & 31;
    const int warp_m = wid & 3, warp_n = wid >> 2;
    const int row0 = blockIdx.y * BM;
    const int col0 = blockIdx.x * BN;

    float acc[2][8][4];
#pragma unroll
    for (int i = 0; i < 2; i++)
#pragma unroll
        for (int j = 0; j < 8; j++)
#pragma unroll
            for (int q = 0; q < 4; q++) acc[i][j][q] = 0.f;

    load_chunk(A, W, sbase, 0, 0, row0, col0, t);
    CP_COMMIT();
    load_chunk(A, W, sbase, 1, 1, row0, col0, t);
    CP_COMMIT();

    const int a_row = lane & 15, a_kb = (lane >> 4) * 16;
    const int b_g = lane >> 3;
    const int b_row = ((b_g >> 1) * 8) + (lane & 7);
    const int b_kb = (b_g & 1) * 16;

    int stage = 0;
    for (int c = 0; c < NCHUNK; c++) {
        if (c == NCHUNK - 1) { CP_WAIT0(); } else { CP_WAIT1(); }
        __syncthreads();
        if (c + 2 < NCHUNK) {
            int ns = stage + 2; if (ns >= NSTAGE) ns -= NSTAGE;
            load_chunk(A, W, sbase, ns, c + 2, row0, col0, t);
            CP_COMMIT();
        }

        unsigned As = sbase + stage * STAGE_BYTES;
        unsigned Bs = As + TILE_BYTES;
#pragma unroll
        for (int ks = 0; ks < 4; ks++) {
            unsigned a[2][4], b[8][2];
#pragma unroll
            for (int mt = 0; mt < 2; mt++) {
                int row = warp_m * 32 + mt * 16 + a_row;
                LDSM4(a[mt], As + SWZ(row * 128 + ks * 32 + a_kb));
            }
#pragma unroll
            for (int np = 0; np < 4; np++) {
                int row = warp_n * 64 + np * 16 + b_row;
                unsigned r4[4];
                LDSM4(r4, Bs + SWZ(row * 128 + ks * 32 + b_kb));
                b[np * 2][0] = r4[0]; b[np * 2][1] = r4[1];
                b[np * 2 + 1][0] = r4[2]; b[np * 2 + 1][1] = r4[3];
            }
#pragma unroll
            for (int mt = 0; mt < 2; mt++)
#pragma unroll
                for (int nt = 0; nt < 8; nt++)
                    MMA16816(acc[mt][nt], a[mt], b[nt]);
        }
        stage++; if (stage >= NSTAGE) stage = 0;
    }

    // Epilogue
#pragma unroll
    for (int mt = 0; mt < 2; mt++) {
        int row = row0 + warp_m * 32 + mt * 16 + (lane >> 2);
#pragma unroll
        for (int nt = 0; nt < 8; nt++) {
            int col = col0 + warp_n * 64 + nt * 8 + (lane & 3) * 2;
            float bv0 = bias[col], bv1 = bias[col + 1];
            float o0 = acc[mt][nt][0] + bv0;
            float o1 = acc[mt][nt][1] + bv1;
            float o2 = acc[mt][nt][2] + bv0;
            float o3 = acc[mt][nt][3] + bv1;
            if (act) {
                o0 = o0 > 0.f ? o0 + 1.f : __expf(o0);
                o1 = o1 > 0.f ? o1 + 1.f : __expf(o1);
                o2 = o2 > 0.f ? o2 + 1.f : __expf(o2);
                o3 = o3 > 0.f ? o3 + 1.f : __expf(o3);
            }
            *(float2*)(C + (size_t)row * D_ + col)       = make_float2(o0, o1);
            *(float2*)(C + (size_t)(row + 8) * D_ + col) = make_float2(o2, o3);
        }
    }
}

__global__ __launch_bounds__(256, 2) void qkv_tc(
    const float* __restrict__ bQ, const float* __restrict__ bK,
    const float* __restrict__ bV)
{
    const int z = blockIdx.z;
    const __nv_bfloat16* W = (z == 0) ? g_Wq : (z == 1) ? g_Wk : g_Wv;
    const float* bb        = (z == 0) ? bQ   : (z == 1) ? bK   : bV;
    float* C               = (z == 0) ? g_phiq : (z == 1) ? g_phik : g_v;
    tc_gemm_body(g_Qs, W, bb, C, z < 2);
}

__global__ __launch_bounds__(256, 2) void out_tc(
    const float* __restrict__ bO, float* __restrict__ out)
{
    tc_gemm_body(g_VNs, g_Wo, bO, out, 0);
}

// ---------------------------------------------------------------------------
// fp32 -> bf16 2-term split, stored [hi | lo] with K2 row stride
// ---------------------------------------------------------------------------
__device__ __forceinline__ void split_one(
    const float* __restrict__ in, __nv_bfloat16* __restrict__ out, size_t i)
{
    const float2 x = ((const float2*)in)[i];
    size_t r = i >> 9;
    int c2 = (int)(i & 511);
    __nv_bfloat16 h0 = __float2bfloat16(x.x), h1 = __float2bfloat16(x.y);
    __nv_bfloat16 l0 = __float2bfloat16(x.x - __bfloat162float(h0));
    __nv_bfloat16 l1 = __float2bfloat16(x.y - __bfloat162float(h1));
    unsigned hv = ((unsigned)__bfloat16_as_ushort(h1) << 16) | __bfloat16_as_ushort(h0);
    unsigned lv = ((unsigned)__bfloat16_as_ushort(l1) << 16) | __bfloat16_as_ushort(l0);
    unsigned* o = (unsigned*)(out + r * K2) + c2;
    o[0] = hv; o[512] = lv;
}

__global__ __launch_bounds__(256) void split_q_kernel(const float* __restrict__ Q)
{
    split_one(Q, g_Qs, (size_t)blockIdx.x * 256 + threadIdx.x);
}

__global__ __launch_bounds__(256) void split_w_kernel(
    const float* __restrict__ WQ, const float* __restrict__ WK,
    const float* __restrict__ WV, const float* __restrict__ WO)
{
    const int z = blockIdx.y;
    const float* in = (z == 0) ? WQ : (z == 1) ? WK : (z == 2) ? WV : WO;
    __nv_bfloat16* out = (z == 0) ? g_Wq : (z == 1) ? g_Wk : (z == 2) ? g_Wv : g_Wo;
    split_one(in, out, (size_t)blockIdx.x * 256 + threadIdx.x);
}

// ---------------------------------------------------------------------------
// Zero accumulators
// ---------------------------------------------------------------------------
__global__ void zero_acc_kernel()
{
    int i = blockIdx.x * 256 + threadIdx.x;
    if (i < 64 * 64 * 64) g_KV[i] = 0.f;
    if (i < 64 * 64)      g_Ksum[i] = 0.f;
}

// ---------------------------------------------------------------------------
// KV[bh][d][m] accumulation + K_sum
// ---------------------------------------------------------------------------
__global__ __launch_bounds__(256) void kv_kernel()
{
    const int bh = blockIdx.x;
    const int b = bh >> 4, h = bh & 15;
    const int l0 = blockIdx.y * 512;

    __shared__ float ks[16][64];
    __shared__ float vs[16][64];

    const int t = threadIdx.x;
    const int td = t >> 4, tmm = t & 15;
    const int lr = t >> 4, lc = (t & 15) * 4;

    float acc[4][4];
    float ksum[4] = {0.f, 0.f, 0.f, 0.f};
#pragma unroll
    for (int i = 0; i < 4; i++)
#pragma unroll
        for (int j = 0; j < 4; j++) acc[i][j] = 0.f;

    for (int lt = 0; lt < 512; lt += 16) {
        size_t base = ((size_t)(b * L_ + l0 + lt + lr)) * D_ + h * 64 + lc;
        float4 kq = *(const float4*)(g_phik + base);
        float4 vq = *(const float4*)(g_v + base);
        __syncthreads();
        *(float4*)&ks[lr][lc] = kq;
        *(float4*)&vs[lr][lc] = vq;
        __syncthreads();
#pragma unroll
        for (int ll = 0; ll < 16; ll++) {
            float ka[4], va[4];
#pragma unroll
            for (int i = 0; i < 4; i++) ka[i] = ks[ll][td * 4 + i];
#pragma unroll
            for (int j = 0; j < 4; j++) va[j] = vs[ll][tmm * 4 + j];
#pragma unroll
            for (int i = 0; i < 4; i++)
#pragma unroll
                for (int j = 0; j < 4; j++) acc[i][j] += ka[i] * va[j];
            if (tmm == 0) {
#pragma unroll
                for (int i = 0; i < 4; i++) ksum[i] += ka[i];
            }
        }
    }

    float* kvout = g_KV + bh * 4096;
#pragma unroll
    for (int i = 0; i < 4; i++)
#pragma unroll
        for (int j = 0; j < 4; j++)
            atomicAdd(&kvout[(td * 4 + i) * 64 + tmm * 4 + j], acc[i][j]);
    if (tmm == 0) {
#pragma unroll
        for (int i = 0; i < 4; i++)
            atomicAdd(&g_Ksum[bh * 64 + td * 4 + i], ksum[i]);
    }
}

// ---------------------------------------------------------------------------
// V_new: warp handles 4 rows per pass; d-loop vectorized (float4 pq reads).
// Writes bf16 split [hi|lo] into g_VNs (K2 stride).
// ---------------------------------------------------------------------------
__global__ __launch_bounds__(256) void vnew_kernel()
{
    const int bh = blockIdx.x;
    const int b = bh >> 4, h = bh & 15;
    const int l0 = blockIdx.y * 512;

    __shared__ float KVs[64][64];
    __shared__ float Ks[64];
    __shared__ float pqs[8][4][64];

    const int t = threadIdx.x, w = t >> 5, lane = t & 31;

    for (int i = t; i < 1024; i += 256)
        ((float4*)KVs)[i] = ((const float4*)(g_KV + bh * 4096))[i];
    if (t < 64) Ks[t] = g_Ksum[bh * 64 + t];
    __syncthreads();

    const int prow = lane >> 3;          // 0..3
    const int pcol = (lane & 7) * 8;     // 0..56

    for (int s = 0; s < 16; s++) {
        const int lb = l0 + s * 32 + w * 4;
        const float* pq = g_phiq + ((size_t)(b * L_ + lb + prow)) * D_ + h * 64 + pcol;
        float4 pa = *(const float4*)pq;
        float4 pb = *(const float4*)(pq + 4);
        *(float4*)&pqs[w][prow][pcol]     = pa;
        *(float4*)&pqs[w][prow][pcol + 4] = pb;

        float zp = pa.x * Ks[pcol]     + pa.y * Ks[pcol + 1]
                 + pa.z * Ks[pcol + 2] + pa.w * Ks[pcol + 3]
                 + pb.x * Ks[pcol + 4] + pb.y * Ks[pcol + 5]
                 + pb.z * Ks[pcol + 6] + pb.w * Ks[pcol + 7];
        zp += __shfl_xor_sync(0xffffffffu, zp, 1);
        zp += __shfl_xor_sync(0xffffffffu, zp, 2);
        zp += __shfl_xor_sync(0xffffffffu, zp, 4);
        float z0 = 1.f / (__shfl_sync(0xffffffffu, zp, 0)  + EPS_);
        float z1 = 1.f / (__shfl_sync(0xffffffffu, zp, 8)  + EPS_);
        float z2 = 1.f / (__shfl_sync(0xffffffffu, zp, 16) + EPS_);
        float z3 = 1.f / (__shfl_sync(0xffffffffu, zp, 24) + EPS_);
        __syncwarp();

        float2 a0 = {0.f, 0.f}, a1 = {0.f, 0.f}, a2 = {0.f, 0.f}, a3 = {0.f, 0.f};
        const float4* q40 = (const float4*)&pqs[w][0][0];
        const float4* q41 = (const float4*)&pqs[w][1][0];
        const float4* q42 = (const float4*)&pqs[w][2][0];
        const float4* q43 = (const float4*)&pqs[w][3][0];
#pragma unroll
        for (int d4 = 0; d4 < 16; d4++) {
            float4 q0 = q40[d4], q1 = q41[d4], q2 = q42[d4], q3 = q43[d4];
            float2 kv0 = *(const float2*)&KVs[d4 * 4 + 0][lane * 2];
            float2 kv1 = *(const float2*)&KVs[d4 * 4 + 1][lane * 2];
            float2 kv2 = *(const float2*)&KVs[d4 * 4 + 2][lane * 2];
            float2 kv3 = *(const float2*)&KVs[d4 * 4 + 3][lane * 2];
            a0.x += q0.x * kv0.x + q0.y * kv1.x + q0.z * kv2.x + q0.w * kv3.x;
            a0.y += q0.x * kv0.y + q0.y * kv1.y + q0.z * kv2.y + q0.w * kv3.y;
            a1.x += q1.x * kv0.x + q1.y * kv1.x + q1.z * kv2.x + q1.w * kv3.x;
            a1.y += q1.x * kv0.y + q1.y * kv1.y + q1.z * kv2.y + q1.w * kv3.y;
            a2.x += q2.x * kv0.x + q2.y * kv1.x + q2.z * kv2.x + q2.w * kv3.x;
            a2.y += q2.x * kv0.y + q2.y * kv1.y + q2.z * kv2.y + q2.w * kv3.y;
            a3.x += q3.x * kv0.x + q3.y * kv1.x + q3.z * kv2.x + q3.w * kv3.x;
            a3.y += q3.x * kv0.y + q3.y * kv1.y + q3.z * kv2.y + q3.w * kv3.y;
        }

        float2 vv[4] = {
            {a0.x * z0, a0.y * z0}, {a1.x * z1, a1.y * z1},
            {a2.x * z2, a2.y * z2}, {a3.x * z3, a3.y * z3}
        };
#pragma unroll
        for (int j = 0; j < 4; j++) {
            __nv_bfloat16 h0 = __float2bfloat16(vv[j].x);
            __nv_bfloat16 h1 = __float2bfloat16(vv[j].y);
            __nv_bfloat16 q0 = __float2bfloat16(vv[j].x - __bfloat162float(h0));
            __nv_bfloat16 q1 = __float2bfloat16(vv[j].y - __bfloat162float(h1));
            unsigned hv = ((unsigned)__bfloat16_as_ushort(h1) << 16) | __bfloat16_as_ushort(h0);
            unsigned lv = ((unsigned)__bfloat16_as_ushort(q1) << 16) | __bfloat16_as_ushort(q0);
            unsigned* p = (unsigned*)(g_VNs + (size_t)(b * L_ + lb + j) * K2) + h * 32 + lane;
            p[0] = hv; p[512] = lv;
        }
        __syncwarp();
    }
}

// ---------------------------------------------------------------------------
// Launch
// ---------------------------------------------------------------------------
extern "C" void kernel_launch(void* const* d_in, const int* in_sizes, int n_in,
                              void* d_out, int out_size)
{
    const float* Q  = (const float*)d_in[0];
    const float* WQ = (const float*)d_in[1];
    const float* bQ = (const float*)d_in[2];
    const float* WK = (const float*)d_in[3];
    const float* bK = (const float*)d_in[4];
    const float* WV = (const float*)d_in[5];
    const float* bV = (const float*)d_in[6];
    const float* WO = (const float*)d_in[7];
    const float* bO = (const float*)d_in[8];
    float* out = (float*)d_out;

    cudaFuncSetAttribute(qkv_tc, cudaFuncAttributeMaxDynamicSharedMemorySize, DSMEM_BYTES);
    cudaFuncSetAttribute(out_tc, cudaFuncAttributeMaxDynamicSharedMemorySize, DSMEM_BYTES);

    zero_acc_kernel<<<1024, 256>>>();

    split_q_kernel<<<(M_ * 512) / 256, 256>>>(Q);
    {
        dim3 grid((D_ * 512) / 256, 4);
        split_w_kernel<<<grid, 256>>>(WQ, WK, WV, WO);
    }

    {
        dim3 grid(D_ / BN, M_ / BM, 3);
        qkv_tc<<<grid, 256, DSMEM_BYTES>>>(bQ, bK, bV);
    }
    {
        dim3 grid(64, 8);
        kv_kernel<<<grid, 256>>>();
    }
    {
        dim3 grid(64, 8);
        vnew_kernel<<<grid, 256>>>();
    }
    {
        dim3 grid(D_ / BN, M_ / BM);
        out_tc<<<grid, 256, DSMEM_BYTES>>>(bO, out);
    }
}

// round 7
// speedup vs baseline: 1.1385x; 1.0523x over previous
#include <cuda_runtime.h>
#include <cuda_bf16.h>
#include <math.h>

// Problem constants
#define B_   4
#define L_   4096
#define D_   1024
#define H_   16
#define M_   (B_ * L_)          // 16384
#define K2   2048               // stored split: [hi | lo]
#define EPS_ 1e-5f

// GEMM tile config: 128x128 CTA tile, 8 warps of 32x64
#define BM 128
#define BN 128
#define BK 64
// Phase 1: 16 stages of {Ah, Bh, Bl} (48 KB), 2-stage ring
// Phase 2: 16 stages of {Al, Bh}     (32 KB), 3-stage ring
#define ST1_BYTES 49152
#define ST2_BYTES 32768
#define DSMEM_BYTES (2 * ST1_BYTES + 1024)   // == 3*ST2_BYTES + 1024

// ---------------------------------------------------------------------------
// Scratch (device globals)
// ---------------------------------------------------------------------------
__device__ __align__(128) __nv_bfloat16 g_Qs [(size_t)M_ * K2];
__device__ __align__(128) __nv_bfloat16 g_VNs[(size_t)M_ * K2];
__device__ __align__(128) __nv_bfloat16 g_Wq [(size_t)D_ * K2];
__device__ __align__(128) __nv_bfloat16 g_Wk [(size_t)D_ * K2];
__device__ __align__(128) __nv_bfloat16 g_Wv [(size_t)D_ * K2];
__device__ __align__(128) __nv_bfloat16 g_Wo [(size_t)D_ * K2];
__device__ __align__(128) float g_phiq[(size_t)M_ * D_];
__device__ __align__(128) float g_phik[(size_t)M_ * D_];
__device__ __align__(128) float g_v   [(size_t)M_ * D_];
__device__ __align__(128) float g_KVp [64 * 8 * 64 * 64];   // per-chunk partials
__device__ __align__(128) float g_Ksp [64 * 8 * 64];

// ---------------------------------------------------------------------------
// Helpers
// ---------------------------------------------------------------------------
__device__ __forceinline__ unsigned smem_u32(const void* p) {
    unsigned a;
    asm("{ .reg .u64 t; cvta.to.shared.u64 t, %1; cvt.u32.u64 %0, t; }"
        : "=r"(a) : "l"(p));
    return a;
}
#define SWZ(o) ((o) ^ ((((unsigned)(o)) >> 3) & 0x70))

#define CP_ASYNC16(dst, src) \
    asm volatile("cp.async.cg.shared.global [%0], [%1], 16;" :: "r"(dst), "l"(src))
#define CP_COMMIT() asm volatile("cp.async.commit_group;" ::: "memory")
#define CP_WAIT1()  asm volatile("cp.async.wait_group 1;" ::: "memory")
#define CP_WAIT0()  asm volatile("cp.async.wait_group 0;" ::: "memory")

#define LDSM4(r, a) \
    asm volatile("ldmatrix.sync.aligned.m8n8.x4.shared.b16 {%0,%1,%2,%3}, [%4];" \
                 : "=r"((r)[0]), "=r"((r)[1]), "=r"((r)[2]), "=r"((r)[3]) : "r"(a))

#define MMA16816(c, a, b0, b1) \
    asm volatile("mma.sync.aligned.m16n8k16.row.col.f32.bf16.bf16.f32 " \
                 "{%0,%1,%2,%3}, {%4,%5,%6,%7}, {%8,%9}, {%0,%1,%2,%3};" \
                 : "+f"((c)[0]), "+f"((c)[1]), "+f"((c)[2]), "+f"((c)[3]) \
                 : "r"((a)[0]), "r"((a)[1]), "r"((a)[2]), "r"((a)[3]),   \
                   "r"(b0), "r"(b1))

// ---------------------------------------------------------------------------
// Loaders: gmem (bf16, K2-stride rows) -> swizzled SMEM (cp.async)
// ---------------------------------------------------------------------------
__device__ __forceinline__ void load_tile(
    const __nv_bfloat16* __restrict__ src, unsigned dst,
    int row0, int kcol, int t)
{
    const int r = t >> 3, cc = t & 7;
#pragma unroll
    for (int i = 0; i < 4; i++) {
        const void* s = src + (size_t)(row0 + r + i * 32) * K2 + kcol + cc * 8;
        CP_ASYNC16(dst + SWZ((r + i * 32) * 128 + cc * 16), s);
    }
}

// ---------------------------------------------------------------------------
// GEMM: C = Ah·Bh + Ah·Bl + Al·Bh (+bias, optional phi)
// 256 threads = 8 warps (4 m x 2 n); warp computes 32x64.
// ---------------------------------------------------------------------------
__device__ __forceinline__ void tc_gemm_body(
    const __nv_bfloat16* __restrict__ A, const __nv_bfloat16* __restrict__ W,
    const float* __restrict__ bias, float* __restrict__ C, int act)
{
    extern __shared__ char dsm_raw[];
    unsigned draw = smem_u32(dsm_raw);
    unsigned sbase = (draw + 1023u) & ~1023u;

    const int t = threadIdx.x;
    const int wid = t >> 5, lane = t & 31;
    const int warp_m = wid & 3, warp_n = wid >> 2;
    const int row0 = blockIdx.y * BM;
    const int col0 = blockIdx.x * BN;

    float acc[2][8][4];
#pragma unroll
    for (int i = 0; i < 2; i++)
#pragma unroll
        for (int j = 0; j < 8; j++)
#pragma unroll
            for (int q = 0; q < 4; q++) acc[i][j][q] = 0.f;

    const int a_row = lane & 15, a_kb = (lane >> 4) * 16;
    const int b_g = lane >> 3;
    const int b_row = ((b_g >> 1) * 8) + (lane & 7);
    const int b_kb = (b_g & 1) * 16;

    // ---------------- Phase 1: Ah·Bh + Ah·Bl (2-stage ring of 48 KB) -------
    {
        // preload stage 0
        load_tile(A, sbase,                 row0, 0,    t);
        load_tile(W, sbase + 16384,         col0, 0,    t);
        load_tile(W, sbase + 32768,         col0, 1024, t);
        CP_COMMIT();

        for (int s = 0; s < 16; s++) {
            if (s + 1 < 16) {
                unsigned nb = sbase + ((s + 1) & 1) * ST1_BYTES;
                load_tile(A, nb,         row0, (s + 1) * 64,        t);
                load_tile(W, nb + 16384, col0, (s + 1) * 64,        t);
                load_tile(W, nb + 32768, col0, 1024 + (s + 1) * 64, t);
                CP_COMMIT();
                CP_WAIT1();
            } else {
                CP_WAIT0();
            }
            __syncthreads();

            unsigned As = sbase + (s & 1) * ST1_BYTES;
            unsigned Bh = As + 16384;
            unsigned Bl = As + 32768;
#pragma unroll
            for (int ks = 0; ks < 4; ks++) {
                unsigned a[2][4];
#pragma unroll
                for (int mt = 0; mt < 2; mt++) {
                    int row = warp_m * 32 + mt * 16 + a_row;
                    LDSM4(a[mt], As + SWZ(row * 128 + ks * 32 + a_kb));
                }
#pragma unroll
                for (int np = 0; np < 4; np++) {
                    int brow = warp_n * 64 + np * 16 + b_row;
                    unsigned boff = SWZ(brow * 128 + ks * 32 + b_kb);
                    unsigned bh4[4], bl4[4];
                    LDSM4(bh4, Bh + boff);
                    MMA16816(acc[0][np * 2],     a[0], bh4[0], bh4[1]);
                    MMA16816(acc[0][np * 2 + 1], a[0], bh4[2], bh4[3]);
                    MMA16816(acc[1][np * 2],     a[1], bh4[0], bh4[1]);
                    MMA16816(acc[1][np * 2 + 1], a[1], bh4[2], bh4[3]);
                    LDSM4(bl4, Bl + boff);
                    MMA16816(acc[0][np * 2],     a[0], bl4[0], bl4[1]);
                    MMA16816(acc[0][np * 2 + 1], a[0], bl4[2], bl4[3]);
                    MMA16816(acc[1][np * 2],     a[1], bl4[0], bl4[1]);
                    MMA16816(acc[1][np * 2 + 1], a[1], bl4[2], bl4[3]);
                }
            }
            __syncthreads();   // before next iter's load overwrites the other buf
        }
    }

    // ---------------- Phase 2: Al·Bh (3-stage ring of 32 KB) ----------------
    {
        load_tile(A, sbase,         row0, 1024, t);
        load_tile(W, sbase + 16384, col0, 0,    t);
        CP_COMMIT();
        load_tile(A, sbase + ST2_BYTES,         row0, 1024 + 64, t);
        load_tile(W, sbase + ST2_BYTES + 16384, col0, 64,        t);
        CP_COMMIT();

        int stage = 0;
        for (int j = 0; j < 16; j++) {
            if (j == 15) { CP_WAIT0(); } else { CP_WAIT1(); }
            __syncthreads();
            if (j + 2 < 16) {
                int ns = stage + 2; if (ns >= 3) ns -= 3;
                unsigned nb = sbase + ns * ST2_BYTES;
                load_tile(A, nb,         row0, 1024 + (j + 2) * 64, t);
                load_tile(W, nb + 16384, col0, (j + 2) * 64,        t);
                CP_COMMIT();
            }

            unsigned As = sbase + stage * ST2_BYTES;
            unsigned Bh = As + 16384;
#pragma unroll
            for (int ks = 0; ks < 4; ks++) {
                unsigned a[2][4];
#pragma unroll
                for (int mt = 0; mt < 2; mt++) {
                    int row = warp_m * 32 + mt * 16 + a_row;
                    LDSM4(a[mt], As + SWZ(row * 128 + ks * 32 + a_kb));
                }
#pragma unroll
                for (int np = 0; np < 4; np++) {
                    int brow = warp_n * 64 + np * 16 + b_row;
                    unsigned bh4[4];
                    LDSM4(bh4, Bh + SWZ(brow * 128 + ks * 32 + b_kb));
                    MMA16816(acc[0][np * 2],     a[0], bh4[0], bh4[1]);
                    MMA16816(acc[0][np * 2 + 1], a[0], bh4[2], bh4[3]);
                    MMA16816(acc[1][np * 2],     a[1], bh4[0], bh4[1]);
                    MMA16816(acc[1][np * 2 + 1], a[1], bh4[2], bh4[3]);
                }
            }
            stage++; if (stage >= 3) stage = 0;
        }
    }

    // Epilogue
#pragma unroll
    for (int mt = 0; mt < 2; mt++) {
        int row = row0 + warp_m * 32 + mt * 16 + (lane >> 2);
#pragma unroll
        for (int nt = 0; nt < 8; nt++) {
            int col = col0 + warp_n * 64 + nt * 8 + (lane & 3) * 2;
            float bv0 = bias[col], bv1 = bias[col + 1];
            float o0 = acc[mt][nt][0] + bv0;
            float o1 = acc[mt][nt][1] + bv1;
            float o2 = acc[mt][nt][2] + bv0;
            float o3 = acc[mt][nt][3] + bv1;
            if (act) {
                o0 = o0 > 0.f ? o0 + 1.f : __expf(o0);
                o1 = o1 > 0.f ? o1 + 1.f : __expf(o1);
                o2 = o2 > 0.f ? o2 + 1.f : __expf(o2);
                o3 = o3 > 0.f ? o3 + 1.f : __expf(o3);
            }
            *(float2*)(C + (size_t)row * D_ + col)       = make_float2(o0, o1);
            *(float2*)(C + (size_t)(row + 8) * D_ + col) = make_float2(o2, o3);
        }
    }
}

__global__ __launch_bounds__(256, 2) void qkv_tc(
    const float* __restrict__ bQ, const float* __restrict__ bK,
    const float* __restrict__ bV)
{
    const int z = blockIdx.z;
    const __nv_bfloat16* W = (z == 0) ? g_Wq : (z == 1) ? g_Wk : g_Wv;
    const float* bb        = (z == 0) ? bQ   : (z == 1) ? bK   : bV;
    float* C               = (z == 0) ? g_phiq : (z == 1) ? g_phik : g_v;
    tc_gemm_body(g_Qs, W, bb, C, z < 2);
}

__global__ __launch_bounds__(256, 2) void out_tc(
    const float* __restrict__ bO, float* __restrict__ out)
{
    tc_gemm_body(g_VNs, g_Wo, bO, out, 0);
}

// ---------------------------------------------------------------------------
// fp32 -> bf16 2-term split, stored [hi | lo] with K2 row stride
// ---------------------------------------------------------------------------
__device__ __forceinline__ void split_one(
    const float* __restrict__ in, __nv_bfloat16* __restrict__ out, size_t i)
{
    const float2 x = ((const float2*)in)[i];
    size_t r = i >> 9;
    int c2 = (int)(i & 511);
    __nv_bfloat16 h0 = __float2bfloat16(x.x), h1 = __float2bfloat16(x.y);
    __nv_bfloat16 l0 = __float2bfloat16(x.x - __bfloat162float(h0));
    __nv_bfloat16 l1 = __float2bfloat16(x.y - __bfloat162float(h1));
    unsigned hv = ((unsigned)__bfloat16_as_ushort(h1) << 16) | __bfloat16_as_ushort(h0);
    unsigned lv = ((unsigned)__bfloat16_as_ushort(l1) << 16) | __bfloat16_as_ushort(l0);
    unsigned* o = (unsigned*)(out + r * K2) + c2;
    o[0] = hv; o[512] = lv;
}

__global__ __launch_bounds__(256) void split_q_kernel(const float* __restrict__ Q)
{
    split_one(Q, g_Qs, (size_t)blockIdx.x * 256 + threadIdx.x);
}

__global__ __launch_bounds__(256) void split_w_kernel(
    const float* __restrict__ WQ, const float* __restrict__ WK,
    const float* __restrict__ WV, const float* __restrict__ WO)
{
    const int z = blockIdx.y;
    const float* in = (z == 0) ? WQ : (z == 1) ? WK : (z == 2) ? WV : WO;
    __nv_bfloat16* out = (z == 0) ? g_Wq : (z == 1) ? g_Wk : (z == 2) ? g_Wv : g_Wo;
    split_one(in, out, (size_t)blockIdx.x * 256 + threadIdx.x);
}

// ---------------------------------------------------------------------------
// KV partial accumulation: block (bh, y) writes its own partial (no atomics)
// ---------------------------------------------------------------------------
__global__ __launch_bounds__(256) void kv_kernel()
{
    const int bh = blockIdx.x;
    const int b = bh >> 4, h = bh & 15;
    const int l0 = blockIdx.y * 512;

    __shared__ float ks[16][64];
    __shared__ float vs[16][64];

    const int t = threadIdx.x;
    const int td = t >> 4, tmm = t & 15;
    const int lr = t >> 4, lc = (t & 15) * 4;

    float acc[4][4];
    float ksum[4] = {0.f, 0.f, 0.f, 0.f};
#pragma unroll
    for (int i = 0; i < 4; i++)
#pragma unroll
        for (int j = 0; j < 4; j++) acc[i][j] = 0.f;

    for (int lt = 0; lt < 512; lt += 16) {
        size_t base = ((size_t)(b * L_ + l0 + lt + lr)) * D_ + h * 64 + lc;
        float4 kq = *(const float4*)(g_phik + base);
        float4 vq = *(const float4*)(g_v + base);
        __syncthreads();
        *(float4*)&ks[lr][lc] = kq;
        *(float4*)&vs[lr][lc] = vq;
        __syncthreads();
#pragma unroll
        for (int ll = 0; ll < 16; ll++) {
            float ka[4], va[4];
#pragma unroll
            for (int i = 0; i < 4; i++) ka[i] = ks[ll][td * 4 + i];
#pragma unroll
            for (int j = 0; j < 4; j++) va[j] = vs[ll][tmm * 4 + j];
#pragma unroll
            for (int i = 0; i < 4; i++)
#pragma unroll
                for (int j = 0; j < 4; j++) acc[i][j] += ka[i] * va[j];
            if (tmm == 0) {
#pragma unroll
                for (int i = 0; i < 4; i++) ksum[i] += ka[i];
            }
        }
    }

    float* kvout = g_KVp + ((size_t)bh * 8 + blockIdx.y) * 4096;
#pragma unroll
    for (int i = 0; i < 4; i++)
#pragma unroll
        for (int j = 0; j < 4; j++)
            kvout[(td * 4 + i) * 64 + tmm * 4 + j] = acc[i][j];
    if (tmm == 0) {
#pragma unroll
        for (int i = 0; i < 4; i++)
            g_Ksp[((size_t)bh * 8 + blockIdx.y) * 64 + td * 4 + i] = ksum[i];
    }
}

// ---------------------------------------------------------------------------
// V_new: sums KV partials, warp handles 4 rows/pass, vectorized d-loop.
// Writes bf16 split [hi|lo] into g_VNs (K2 stride).
// ---------------------------------------------------------------------------
__global__ __launch_bounds__(256) void vnew_kernel()
{
    const int bh = blockIdx.x;
    const int b = bh >> 4, h = bh & 15;
    const int l0 = blockIdx.y * 512;

    __shared__ float KVs[64][64];
    __shared__ float Ks[64];
    __shared__ float pqs[8][4][64];

    const int t = threadIdx.x, w = t >> 5, lane = t & 31;

    for (int i = t; i < 1024; i += 256) {
        float4 s = make_float4(0.f, 0.f, 0.f, 0.f);
#pragma unroll
        for (int p = 0; p < 8; p++) {
            float4 v = ((const float4*)(g_KVp + ((size_t)bh * 8 + p) * 4096))[i];
            s.x += v.x; s.y += v.y; s.z += v.z; s.w += v.w;
        }
        ((float4*)KVs)[i] = s;
    }
    if (t < 64) {
        float s = 0.f;
#pragma unroll
        for (int p = 0; p < 8; p++) s += g_Ksp[((size_t)bh * 8 + p) * 64 + t];
        Ks[t] = s;
    }
    __syncthreads();

    const int prow = lane >> 3;          // 0..3
    const int pcol = (lane & 7) * 8;     // 0..56

    for (int s = 0; s < 16; s++) {
        const int lb = l0 + s * 32 + w * 4;
        const float* pq = g_phiq + ((size_t)(b * L_ + lb + prow)) * D_ + h * 64 + pcol;
        float4 pa = *(const float4*)pq;
        float4 pb = *(const float4*)(pq + 4);
        *(float4*)&pqs[w][prow][pcol]     = pa;
        *(float4*)&pqs[w][prow][pcol + 4] = pb;

        float zp = pa.x * Ks[pcol]     + pa.y * Ks[pcol + 1]
                 + pa.z * Ks[pcol + 2] + pa.w * Ks[pcol + 3]
                 + pb.x * Ks[pcol + 4] + pb.y * Ks[pcol + 5]
                 + pb.z * Ks[pcol + 6] + pb.w * Ks[pcol + 7];
        zp += __shfl_xor_sync(0xffffffffu, zp, 1);
        zp += __shfl_xor_sync(0xffffffffu, zp, 2);
        zp += __shfl_xor_sync(0xffffffffu, zp, 4);
        float z0 = 1.f / (__shfl_sync(0xffffffffu, zp, 0)  + EPS_);
        float z1 = 1.f / (__shfl_sync(0xffffffffu, zp, 8)  + EPS_);
        float z2 = 1.f / (__shfl_sync(0xffffffffu, zp, 16) + EPS_);
        float z3 = 1.f / (__shfl_sync(0xffffffffu, zp, 24) + EPS_);
        __syncwarp();

        float2 a0 = {0.f, 0.f}, a1 = {0.f, 0.f}, a2 = {0.f, 0.f}, a3 = {0.f, 0.f};
        const float4* q40 = (const float4*)&pqs[w][0][0];
        const float4* q41 = (const float4*)&pqs[w][1][0];
        const float4* q42 = (const float4*)&pqs[w][2][0];
        const float4* q43 = (const float4*)&pqs[w][3][0];
#pragma unroll
        for (int d4 = 0; d4 < 16; d4++) {
            float4 q0 = q40[d4], q1 = q41[d4], q2 = q42[d4], q3 = q43[d4];
            float2 kv0 = *(const float2*)&KVs[d4 * 4 + 0][lane * 2];
            float2 kv1 = *(const float2*)&KVs[d4 * 4 + 1][lane * 2];
            float2 kv2 = *(const float2*)&KVs[d4 * 4 + 2][lane * 2];
            float2 kv3 = *(const float2*)&KVs[d4 * 4 + 3][lane * 2];
            a0.x += q0.x * kv0.x + q0.y * kv1.x + q0.z * kv2.x + q0.w * kv3.x;
            a0.y += q0.x * kv0.y + q0.y * kv1.y + q0.z * kv2.y + q0.w * kv3.y;
            a1.x += q1.x * kv0.x + q1.y * kv1.x + q1.z * kv2.x + q1.w * kv3.x;
            a1.y += q1.x * kv0.y + q1.y * kv1.y + q1.z * kv2.y + q1.w * kv3.y;
            a2.x += q2.x * kv0.x + q2.y * kv1.x + q2.z * kv2.x + q2.w * kv3.x;
            a2.y += q2.x * kv0.y + q2.y * kv1.y + q2.z * kv2.y + q2.w * kv3.y;
            a3.x += q3.x * kv0.x + q3.y * kv1.x + q3.z * kv2.x + q3.w * kv3.x;
            a3.y += q3.x * kv0.y + q3.y * kv1.y + q3.z * kv2.y + q3.w * kv3.y;
        }

        float2 vv[4] = {
            {a0.x * z0, a0.y * z0}, {a1.x * z1, a1.y * z1},
            {a2.x * z2, a2.y * z2}, {a3.x * z3, a3.y * z3}
        };
#pragma unroll
        for (int j = 0; j < 4; j++) {
            __nv_bfloat16 h0 = __float2bfloat16(vv[j].x);
            __nv_bfloat16 h1 = __float2bfloat16(vv[j].y);
            __nv_bfloat16 q0 = __float2bfloat16(vv[j].x - __bfloat162float(h0));
            __nv_bfloat16 q1 = __float2bfloat16(vv[j].y - __bfloat162float(h1));
            unsigned hv = ((unsigned)__bfloat16_as_ushort(h1) << 16) | __bfloat16_as_ushort(h0);
            unsigned lv = ((unsigned)__bfloat16_as_ushort(q1) << 16) | __bfloat16_as_ushort(q0);
            unsigned* p = (unsigned*)(g_VNs + (size_t)(b * L_ + lb + j) * K2) + h * 32 + lane;
            p[0] = hv; p[512] = lv;
        }
        __syncwarp();
    }
}

// ---------------------------------------------------------------------------
// Launch
// ---------------------------------------------------------------------------
extern "C" void kernel_launch(void* const* d_in, const int* in_sizes, int n_in,
                              void* d_out, int out_size)
{
    const float* Q  = (const float*)d_in[0];
    const float* WQ = (const float*)d_in[1];
    const float* bQ = (const float*)d_in[2];
    const float* WK = (const float*)d_in[3];
    const float* bK = (const float*)d_in[4];
    const float* WV = (const float*)d_in[5];
    const float* bV = (const float*)d_in[6];
    const float* WO = (const float*)d_in[7];
    const float* bO = (const float*)d_in[8];
    float* out = (float*)d_out;

    cudaFuncSetAttribute(qkv_tc, cudaFuncAttributeMaxDynamicSharedMemorySize, DSMEM_BYTES);
    cudaFuncSetAttribute(out_tc, cudaFuncAttributeMaxDynamicSharedMemorySize, DSMEM_BYTES);

    split_q_kernel<<<(M_ * 512) / 256, 256>>>(Q);
    {
        dim3 grid((D_ * 512) / 256, 4);
        split_w_kernel<<<grid, 256>>>(WQ, WK, WV, WO);
    }

    {
        dim3 grid(D_ / BN, M_ / BM, 3);
        qkv_tc<<<grid, 256, DSMEM_BYTES>>>(bQ, bK, bV);
    }
    {
        dim3 grid(64, 8);
        kv_kernel<<<grid, 256>>>();
    }
    {
        dim3 grid(64, 8);
        vnew_kernel<<<grid, 256>>>();
    }
    {
        dim3 grid(D_ / BN, M_ / BM);
        out_tc<<<grid, 256, DSMEM_BYTES>>>(bO, out);
    }
}